// round 6
// baseline (speedup 1.0000x reference)
#include <cuda_runtime.h>
#include <cstdint>

// Dendrite_755914244697 — persistent double-buffered cp.async.bulk pipeline.
// 4 CTAs/SM x 256 threads (32 warps/SM); each OUTPUT is split across a lane
// pair (lane 2i: k=0..12, lane 2i+1: k=13..24), combined with shfl_xor(1).
// out[o] = log( prod_{k<25} (1.1 + atan(10*(p[k]*w[o*25+k] - q[o*25+k]))/pi) )

#define IMG   128
#define OUTD  124
#define SIDE  5
#define SEG   25
#define TPB   256
#define TILE  128
#define NS    2
#define KH    13                               // k-elements per lane (padded)
#define TILE_BYTES  (TILE * SEG * 4)           // 12800 B per array per tile
#define STAGE_BYTES (2 * TILE_BYTES)           // w + q = 25600 B
#define SMEM_BYTES  (256 + NS * STAGE_BYTES)   // 51456 B per CTA

__device__ __forceinline__ uint32_t smem_u32(const void* p)
{
    uint32_t a;
    asm("{ .reg .u64 t; cvta.to.shared.u64 t, %1; cvt.u32.u64 %0, t; }"
        : "=r"(a) : "l"(p));
    return a;
}

__device__ __forceinline__ void mbar_init(uint32_t mb, uint32_t count)
{
    asm volatile("mbarrier.init.shared.b64 [%0], %1;" :: "r"(mb), "r"(count) : "memory");
}

__device__ __forceinline__ void mbar_expect_tx(uint32_t mb, uint32_t bytes)
{
    asm volatile("mbarrier.arrive.expect_tx.shared.b64 _, [%0], %1;"
                 :: "r"(mb), "r"(bytes) : "memory");
}

__device__ __forceinline__ void bulk_g2s(uint32_t dst, const void* src,
                                         uint32_t bytes, uint32_t mb)
{
    asm volatile("cp.async.bulk.shared::cta.global.mbarrier::complete_tx::bytes "
                 "[%0], [%1], %2, [%3];"
                 :: "r"(dst), "l"(src), "r"(bytes), "r"(mb) : "memory");
}

__device__ __forceinline__ void mbar_wait(uint32_t mb, uint32_t phase)
{
    uint32_t done;
    asm volatile(
        "{ .reg .pred p;\n"
        "  mbarrier.try_wait.parity.acquire.cta.shared::cta.b64 p, [%1], %2;\n"
        "  selp.b32 %0, 1, 0, p; }"
        : "=r"(done) : "r"(mb), "r"(phase) : "memory");
    while (!done) {
        asm volatile(
            "{ .reg .pred p;\n"
            "  mbarrier.try_wait.parity.acquire.cta.shared::cta.b64 p, [%1], %2, 0x989680;\n"
            "  selp.b32 %0, 1, 0, p; }"
            : "=r"(done) : "r"(mb), "r"(phase) : "memory");
    }
}

// v(u) = 1.1 + atan(u)/pi. 5-coeff minimax (max err ~1e-5 rad).
__device__ __forceinline__ float v_of(float u)
{
    float inv;
    asm("rcp.approx.f32 %0, %1;" : "=f"(inv) : "f"(u));   // signed reciprocal
    bool  big = fabsf(u) > 1.0f;
    float z   = big ? inv : u;
    float s   = z * z;
    float p   =              0.0208351f;
    p = __fmaf_rn(p, s, -0.0851330f);
    p = __fmaf_rn(p, s,  0.1801410f);
    p = __fmaf_rn(p, s, -0.3302995f);
    p = __fmaf_rn(p, s,  0.9998660f);
    float r = p * z;                                       // atan(z), signed
    float c = __uint_as_float(0x3fc90fdbu |
                              (__float_as_uint(u) & 0x80000000u));
    float a = big ? (c - r) : r;
    return __fmaf_rn(a, 0.31830988618379067f, 1.1f);
}

__global__ void __launch_bounds__(TPB, 4)
dendrite_kernel(const float* __restrict__ x,
                const float* __restrict__ w,
                const float* __restrict__ q,
                float*       __restrict__ out,
                int n_out)
{
    extern __shared__ char smem[];
    const uint32_t sb  = smem_u32(smem);
    const uint32_t mb0 = sb;                       // NS mbarriers at [0, 16)
    float* buf = reinterpret_cast<float*>(smem + 256);

    const int tid = threadIdx.x;

    if (tid == 0) {
#pragma unroll
        for (int i = 0; i < NS; ++i) mbar_init(mb0 + 8 * i, 1);
        asm volatile("fence.proxy.async.shared::cta;" ::: "memory");
    }
    __syncthreads();

    const int ntiles = (n_out + TILE - 1) / TILE;
    int t = blockIdx.x;
    if (t >= ntiles) return;
    const int G = gridDim.x;

    auto issue = [&](int st, int tile) {
        const int cnt     = min(TILE, n_out - tile * TILE);
        const uint32_t nb = (uint32_t)cnt * SEG * 4;     // multiple of 16 here
        const uint32_t mb = mb0 + st * 8;
        const uint32_t dw = sb + 256 + st * STAGE_BYTES;
        const size_t  off = (size_t)tile * TILE_BYTES;
        mbar_expect_tx(mb, 2 * nb);
        bulk_g2s(dw,              (const char*)w + off, nb, mb);
        bulk_g2s(dw + TILE_BYTES, (const char*)q + off, nb, mb);
    };

    if (tid == 0) issue(0, t);     // prefill stage 0

    const float LN2 = 0.69314718055994531f;

    const int lo   = tid >> 1;         // local output index 0..127
    const int h    = tid & 1;          // which half of the 25-element segment
    const int kbeg = h ? 12 : 0;       // half0: k=0..12 ; half1: k=12..24
                                       // (k=12 duplicated; half1 pads it to 1.0)

    for (int j = 0; t < ntiles; ++j, t += G) {
        const int s = j & 1;

        // Refill the other stage (freed by last iteration's __syncthreads).
        if (tid == 0) {
            const int tn = t + G;
            if (tn < ntiles) issue(s ^ 1, tn);
        }

        // ---- x-patch loads: independent of staged data, hide under the copy ----
        const int o  = t * TILE + lo;
        const bool active = (o < n_out);
        const int oc = active ? o : (n_out - 1);
        {
        }
        const int sp = oc / 25;
        const int c  = sp / (OUTD * OUTD);
        const int rr = sp - c * (OUTD * OUTD);
        const int oy = rr / OUTD;
        const int ox = rr - oy * OUTD;
        const float* __restrict__ xp = x + (c * IMG + oy) * IMG + ox;

        float pv[KH];
#pragma unroll
        for (int i = 0; i < KH; ++i) {
            const int k0 = i;            // half 0 k
            const int k1 = 12 + i;       // half 1 k
            const int off0 = (k0 / 5) * IMG + (k0 % 5);
            const int off1 = (k1 / 5) * IMG + (k1 % 5);
            pv[i] = __ldg(xp + (h ? off1 : off0));
        }

        mbar_wait(mb0 + s * 8, (uint32_t)(j >> 1) & 1u);

        {
            const float* wr = buf + s * (STAGE_BYTES / 4) + lo * SEG + kbeg;
            const float* qr = wr + TILE_BYTES / 4;

            float pr0 = 1.0f, pr1 = 1.0f, pr2 = 1.0f;
#pragma unroll
            for (int i = 0; i < KH; ++i) {
                float tt = __fmaf_rn(pv[i], wr[i], -qr[i]);
                float v  = v_of(10.0f * tt);
                if (i == 0 && h) v = 1.0f;   // half1 skips the duplicated k=12
                if      (i % 3 == 0) pr0 *= v;
                else if (i % 3 == 1) pr1 *= v;
                else                 pr2 *= v;
            }
            float myp  = (pr0 * pr1) * pr2;
            float othp = __shfl_xor_sync(0xffffffffu, myp, 1);
            if (active && h == 0)
                out[o] = __log2f(myp * othp) * LN2;
        }
        __syncthreads();   // stage s fully consumed -> refillable next iteration
    }
}

extern "C" void kernel_launch(void* const* d_in, const int* in_sizes, int n_in,
                              void* d_out, int out_size)
{
    const float* x = (const float*)d_in[0];
    const float* w = (const float*)d_in[1];
    const float* q = (const float*)d_in[2];
    float* out = (float*)d_out;

    cudaFuncSetAttribute(dendrite_kernel,
                         cudaFuncAttributeMaxDynamicSharedMemorySize, SMEM_BYTES);

    int sm = 148;
    cudaDeviceGetAttribute(&sm, cudaDevAttrMultiProcessorCount, 0);

    const int n_out  = out_size;                     // 1,153,200
    const int ntiles = (n_out + TILE - 1) / TILE;    // 9010
    int grid = sm * 4;
    if (grid > ntiles) grid = ntiles;

    dendrite_kernel<<<grid, TPB, SMEM_BYTES>>>(x, w, q, out, n_out);
}